// round 7
// baseline (speedup 1.0000x reference)
#include <cuda_runtime.h>
#include <cuda_bf16.h>
#include <math.h>
#include <stdint.h>

#define D_MODEL 512
#define D_LOW   64
#define NUM_BINS 39
#define NB_PAD  40
#define DIST_MIN_F 2.0f
#define DIST_MAX_F 22.0f
#define BIN_W  ((DIST_MAX_F - DIST_MIN_F) / (float)(NUM_BINS - 1))
#define LN_EPS 1e-5f
#define MAX_ROWS 4096
#define JT 128

__device__ float g_U[MAX_ROWS * D_LOW];
__device__ unsigned long long g_Vb[MAX_ROWS * (D_LOW / 4)];  // 4 bf16 per u64
__device__ float g_Wt[D_MODEL * 128];
__device__ double g_ce[8];
__device__ unsigned int g_cnt[8];
__device__ unsigned int g_done;

__device__ __forceinline__ uint32_t smem_u32(const void* p) {
    uint32_t a;
    asm("{ .reg .u64 t; cvta.to.shared.u64 t, %1; cvt.u32.u64 %0, t; }" : "=r"(a) : "l"(p));
    return a;
}
#define CVT_BF2(res, lo, hi) \
    asm("cvt.rn.satfinite.bf16x2.f32 %0, %1, %2;" : "=r"(res) : "f"(hi), "f"(lo))
#define MULBF2(res, a, b) \
    asm("mul.bf16x2 %0, %1, %2;" : "=r"(res) : "r"(a), "r"(b))

#define LDSM_X4(r0, r1, r2, r3, addr) \
    asm volatile("ldmatrix.sync.aligned.m8n8.x4.shared.b16 {%0,%1,%2,%3}, [%4];" \
                 : "=r"(r0), "=r"(r1), "=r"(r2), "=r"(r3) : "r"(addr))

#define MMA_BF16(d, a0, a1, a2, a3, b0, b1) \
    asm volatile("mma.sync.aligned.m16n8k16.row.col.f32.bf16.bf16.f32 " \
                 "{%0,%1,%2,%3}, {%4,%5,%6,%7}, {%8,%9}, {%0,%1,%2,%3};" \
                 : "+f"((d)[0]), "+f"((d)[1]), "+f"((d)[2]), "+f"((d)[3]) \
                 : "r"(a0), "r"(a1), "r"(a2), "r"(a3), "r"(b0), "r"(b1))

// ---------------------------------------------------------------------------
// Kernel 0: transpose wu/wv into c-major Wt[512][128]; zero accumulators.
// ---------------------------------------------------------------------------
__global__ void __launch_bounds__(256) transpose_kernel(
    const float* __restrict__ wu_w, const float* __restrict__ wv_w)
{
    int idx = blockIdx.x * 256 + threadIdx.x;
    int c = idx >> 7;
    int o = idx & 127;
    float v = (o < D_LOW) ? wu_w[(size_t)o * D_MODEL + c]
                          : wv_w[(size_t)(o - D_LOW) * D_MODEL + c];
    g_Wt[idx] = v;
    if (idx < 8) { g_ce[idx] = 0.0; g_cnt[idx] = 0u; }
    if (idx == 8) g_done = 0u;
}

// ---------------------------------------------------------------------------
// Kernel 1: LayerNorm + projections. U -> fp32, V -> bf16 packed.
// ---------------------------------------------------------------------------
#define TR 16

__global__ void __launch_bounds__(256) prep_kernel(
    const float* __restrict__ h_res,
    const float* __restrict__ ln_w, const float* __restrict__ ln_b,
    const float* __restrict__ wu_b, const float* __restrict__ wv_b)
{
    __shared__ __align__(16) float sh[TR * D_MODEL];

    int t    = threadIdx.x;
    int warp = t >> 5;
    int lane = t & 31;

    #pragma unroll
    for (int rr = 0; rr < 2; rr++) {
        int lr  = warp * 2 + rr;
        size_t row = (size_t)blockIdx.x * TR + lr;
        const float4* hp = reinterpret_cast<const float4*>(h_res) + row * (D_MODEL / 4);
        float4 a[4];
        #pragma unroll
        for (int q = 0; q < 4; q++) a[q] = hp[lane + 32 * q];
        float s = 0.0f, sq = 0.0f;
        #pragma unroll
        for (int q = 0; q < 4; q++) {
            s  += a[q].x + a[q].y + a[q].z + a[q].w;
            sq += a[q].x*a[q].x + a[q].y*a[q].y + a[q].z*a[q].z + a[q].w*a[q].w;
        }
        #pragma unroll
        for (int o = 16; o > 0; o >>= 1) {
            s  += __shfl_xor_sync(0xffffffffu, s,  o);
            sq += __shfl_xor_sync(0xffffffffu, sq, o);
        }
        float mu   = s * (1.0f / (float)D_MODEL);
        float var  = sq * (1.0f / (float)D_MODEL) - mu * mu;
        float istd = rsqrtf(var + LN_EPS);

        const float4* wp = reinterpret_cast<const float4*>(ln_w);
        const float4* bp = reinterpret_cast<const float4*>(ln_b);
        float4* shp = reinterpret_cast<float4*>(sh) + lr * (D_MODEL / 4);
        #pragma unroll
        for (int q = 0; q < 4; q++) {
            float4 w4 = wp[lane + 32 * q];
            float4 b4 = bp[lane + 32 * q];
            float4 nv;
            nv.x = (a[q].x - mu) * istd * w4.x + b4.x;
            nv.y = (a[q].y - mu) * istd * w4.y + b4.y;
            nv.z = (a[q].z - mu) * istd * w4.z + b4.z;
            nv.w = (a[q].w - mu) * istd * w4.w + b4.w;
            shp[lane + 32 * q] = nv;
        }
    }
    __syncthreads();

    int tx = t & 31;
    int ty = t >> 5;
    int r0 = ty * 2, r1 = r0 + 1;

    float acc[8];
    #pragma unroll
    for (int q = 0; q < 8; q++) acc[q] = 0.0f;

    const float* sh0 = sh + r0 * D_MODEL;
    const float* sh1 = sh + r1 * D_MODEL;

    #pragma unroll 4
    for (int c = 0; c < D_MODEL; c++) {
        float4 w = *reinterpret_cast<const float4*>(g_Wt + c * 128 + tx * 4);
        float h0 = sh0[c];
        float h1 = sh1[c];
        acc[0] = fmaf(h0, w.x, acc[0]);
        acc[1] = fmaf(h0, w.y, acc[1]);
        acc[2] = fmaf(h0, w.z, acc[2]);
        acc[3] = fmaf(h0, w.w, acc[3]);
        acc[4] = fmaf(h1, w.x, acc[4]);
        acc[5] = fmaf(h1, w.y, acc[5]);
        acc[6] = fmaf(h1, w.z, acc[6]);
        acc[7] = fmaf(h1, w.w, acc[7]);
    }

    size_t grow0 = (size_t)blockIdx.x * TR + r0;
    size_t grow1 = grow0 + 1;
    int col = tx * 4;
    if (col < D_LOW) {
        float4 b = *reinterpret_cast<const float4*>(wu_b + col);
        float4 o0 = make_float4(acc[0] + b.x, acc[1] + b.y, acc[2] + b.z, acc[3] + b.w);
        float4 o1 = make_float4(acc[4] + b.x, acc[5] + b.y, acc[6] + b.z, acc[7] + b.w);
        *reinterpret_cast<float4*>(g_U + grow0 * D_LOW + col) = o0;
        *reinterpret_cast<float4*>(g_U + grow1 * D_LOW + col) = o1;
    } else {
        int vc = col - D_LOW;
        float4 b = *reinterpret_cast<const float4*>(wv_b + vc);
        float v0x = acc[0] + b.x, v0y = acc[1] + b.y, v0z = acc[2] + b.z, v0w = acc[3] + b.w;
        float v1x = acc[4] + b.x, v1y = acc[5] + b.y, v1z = acc[6] + b.z, v1w = acc[7] + b.w;
        uint32_t lo, hi;
        CVT_BF2(lo, v0x, v0y); CVT_BF2(hi, v0z, v0w);
        g_Vb[grow0 * 16 + (vc >> 2)] = (unsigned long long)lo | ((unsigned long long)hi << 32);
        CVT_BF2(lo, v1x, v1y); CVT_BF2(hi, v1z, v1w);
        g_Vb[grow1 * 16 + (vc >> 2)] = (unsigned long long)lo | ((unsigned long long)hi << 32);
    }
}

// ---------------------------------------------------------------------------
// Kernel 2: mma.sync bilinear + register-resident softmax-CE (no D smem
// roundtrip). CTA = one token i; warp = 32 pairs/chunk; last CTA finalizes.
// ---------------------------------------------------------------------------
#define WSTRIDE 144           // bytes per W row (128B data + 16B pad)

__global__ void __launch_bounds__(128) main_kernel(
    const float* __restrict__ x_true, const float* __restrict__ pad,
    const float* __restrict__ wb_w,  const float* __restrict__ wb_b,
    int B, int N, float* __restrict__ out, int total_ctas)
{
    __shared__ uint4 s_V[JT * 9];                 // 18432 B
    __shared__ char  s_W[4][32 * WSTRIDE];        // 18432 B (per-warp W tiles)
    __shared__ uint32_t s_Wb[NB_PAD * 32];        // 5120 B
    __shared__ uint32_t s_U[32];
    __shared__ float s_wbb[NB_PAD];
    __shared__ float s_xi[4];
    __shared__ float s_red[4];
    __shared__ unsigned s_redc[4];

    int tid  = threadIdx.x;
    int wid  = tid >> 5;
    int lane = tid & 31;
    int g    = lane >> 2;       // group row (0..7)
    int tig  = lane & 3;        // thread in group
    int r = blockIdx.x;         // b*N + i
    int b = r / N;

    for (int idx = tid; idx < NB_PAD * 32; idx += 128) {
        int row = idx >> 5, cp = idx & 31;
        float f0 = 0.0f, f1 = 0.0f;
        if (row < NUM_BINS) {
            f0 = wb_w[row * D_LOW + cp * 2];
            f1 = wb_w[row * D_LOW + cp * 2 + 1];
        }
        uint32_t v; CVT_BF2(v, f0, f1);
        s_Wb[idx] = v;
    }
    if (tid < 32) {
        float f0 = g_U[(size_t)r * D_LOW + tid * 2];
        float f1 = g_U[(size_t)r * D_LOW + tid * 2 + 1];
        uint32_t v; CVT_BF2(v, f0, f1);
        s_U[tid] = v;
    }
    if (tid < NB_PAD) s_wbb[tid] = (tid < NUM_BINS) ? wb_b[tid] : 0.0f;
    if (tid == 0) {
        size_t xb = (size_t)r * 3;
        s_xi[0] = x_true[xb]; s_xi[1] = x_true[xb + 1]; s_xi[2] = x_true[xb + 2];
        s_xi[3] = pad[r];
    }
    __syncthreads();

    // B fragments (constant across chunks)
    uint32_t breg[40];
    #pragma unroll
    for (int ks = 0; ks < 4; ks++) {
        #pragma unroll
        for (int nt = 0; nt < 5; nt++) {
            int row = nt * 8 + g;
            int cp  = ks * 8 + tig;
            breg[ks * 10 + nt * 2 + 0] = s_Wb[row * 32 + cp];
            breg[ks * 10 + nt * 2 + 1] = s_Wb[row * 32 + cp + 4];
        }
    }
    // per-thread bias for this thread's columns: col = nt*8 + 2*tig + par
    float bbr[10];
    #pragma unroll
    for (int nt = 0; nt < 5; nt++) {
        bbr[nt * 2 + 0] = s_wbb[nt * 8 + 2 * tig];
        bbr[nt * 2 + 1] = s_wbb[nt * 8 + 2 * tig + 1];
    }

    float xi0 = s_xi[0], xi1 = s_xi[1], xi2 = s_xi[2], pi = s_xi[3];
    const uint4* u4 = reinterpret_cast<const uint4*>(s_U);
    char* sWw = s_W[wid];
    uint32_t sW_base = smem_u32(sWw);

    float cv = 0.0f; unsigned cc = 0u;
    int nchunks = (N + JT - 1) / JT;

    for (int jc = 0; jc < nchunks; jc++) {
        __syncwarp();
        int jw = jc * JT + wid * 32;

        // stage this warp's 32 V rows (coalesced, 8 lanes per 128B row)
        {
            const uint4* src = reinterpret_cast<const uint4*>(g_Vb) + ((size_t)b * N) * 8;
            #pragma unroll
            for (int it = 0; it < 8; it++) {
                int idx = it * 32 + lane;
                int row = idx >> 3, q = idx & 7;
                int j = jw + row;
                uint4 v = make_uint4(0u, 0u, 0u, 0u);
                if (j < N) v = src[(size_t)j * 8 + q];
                s_V[(wid * 32 + row) * 9 + q] = v;
            }
        }
        __syncwarp();

        // W[lane][c] = U[c]*V[j][c] (bf16) -> per-warp smem tile
        {
            const uint4* vr = s_V + (wid * 32 + lane) * 9;
            #pragma unroll
            for (int q = 0; q < 8; q++) {
                uint4 vv = vr[q];
                uint4 uu = u4[q];
                uint4 w;
                MULBF2(w.x, vv.x, uu.x);
                MULBF2(w.y, vv.y, uu.y);
                MULBF2(w.z, vv.z, uu.z);
                MULBF2(w.w, vv.w, uu.w);
                *reinterpret_cast<uint4*>(sWw + lane * WSTRIDE + q * 16) = w;
            }
        }
        __syncwarp();

        float acc[2][5][4];
        #pragma unroll
        for (int m = 0; m < 2; m++)
            #pragma unroll
            for (int nt = 0; nt < 5; nt++)
                #pragma unroll
                for (int q = 0; q < 4; q++) acc[m][nt][q] = 0.0f;

        #pragma unroll
        for (int m = 0; m < 2; m++) {
            #pragma unroll
            for (int ks = 0; ks < 4; ks++) {
                uint32_t a0, a1, a2, a3;
                uint32_t addr = sW_base + (uint32_t)((m * 16 + (lane & 15)) * WSTRIDE
                                                     + ks * 32 + (lane >> 4) * 16);
                LDSM_X4(a0, a1, a2, a3, addr);
                #pragma unroll
                for (int nt = 0; nt < 5; nt++)
                    MMA_BF16(acc[m][nt], a0, a1, a2, a3,
                             breg[ks * 10 + nt * 2], breg[ks * 10 + nt * 2 + 1]);
            }
        }

        // register-resident epilogue: 4 rows per thread (p=0..3)
        #pragma unroll
        for (int p = 0; p < 4; p++) {
            int m = p >> 1;
            int qb = (p & 1) * 2;
            int row = g + 8 * p;            // rows: g, g+8, g+16, g+24
            int j = jw + row;

            float xj0 = 0.f, xj1 = 0.f, xj2 = 0.f, pj = 0.f;
            if (j < N) {
                size_t xb = ((size_t)b * N + j) * 3;
                xj0 = x_true[xb]; xj1 = x_true[xb + 1]; xj2 = x_true[xb + 2];
                pj = pad[(size_t)b * N + j];
            }
            float dx = xi0 - xj0, dy = xi1 - xj1, dz = xi2 - xj2;
            float dist = sqrtf(dx * dx + dy * dy + dz * dz);
            int bin = (int)((dist - DIST_MIN_F) / BIN_W);
            bin = min(max(bin, 0), NUM_BINS - 1);
            int bnt = bin >> 3;
            int btg = (bin & 7) >> 1;
            int bpar = bin & 1;

            float s = 0.0f, tl = 0.0f;
            #pragma unroll
            for (int nt = 0; nt < 5; nt++) {
                float l0 = acc[m][nt][qb]     + bbr[nt * 2];
                float l1 = acc[m][nt][qb + 1] + bbr[nt * 2 + 1];
                float e0 = __expf(l0);
                float e1 = __expf(l1);
                if (nt == 4 && tig == 3) e1 = 0.0f;   // padded col 39
                s += e0 + e1;
                if (nt == bnt && tig == btg) tl += bpar ? l1 : l0;
            }
            // reduce across the 4 group threads
            s  += __shfl_xor_sync(0xffffffffu, s, 1);
            s  += __shfl_xor_sync(0xffffffffu, s, 2);
            tl += __shfl_xor_sync(0xffffffffu, tl, 1);
            tl += __shfl_xor_sync(0xffffffffu, tl, 2);

            float ce = __logf(s) - tl;
            bool ok = (j < N) && (pi * pj > 0.0f);
            if (tig == 0) {
                cv += ok ? ce : 0.0f;
                cc += ok ? 1u : 0u;
            }
        }
    }

    #pragma unroll
    for (int o = 16; o > 0; o >>= 1) {
        cv += __shfl_down_sync(0xffffffffu, cv, o);
        cc += __shfl_down_sync(0xffffffffu, cc, o);
    }
    if (lane == 0) { s_red[wid] = cv; s_redc[wid] = cc; }
    __syncthreads();
    if (tid == 0) {
        float S = s_red[0] + s_red[1] + s_red[2] + s_red[3];
        unsigned C = s_redc[0] + s_redc[1] + s_redc[2] + s_redc[3];
        atomicAdd(&g_ce[b], (double)S);
        atomicAdd(&g_cnt[b], C);
        __threadfence();
        unsigned done = atomicAdd(&g_done, 1u);
        if (done == (unsigned)(total_ctas - 1)) {
            __threadfence();
            double loss = 0.0;
            int valid = 0;
            for (int bb = 0; bb < B; bb++) {
                if (g_cnt[bb] > 0u) { loss += g_ce[bb] / (double)g_cnt[bb]; valid++; }
            }
            out[0] = (float)(valid > 0 ? loss / (double)valid : 0.0);
        }
    }
}

// ---------------------------------------------------------------------------
extern "C" void kernel_launch(void* const* d_in, const int* in_sizes, int n_in,
                              void* d_out, int out_size)
{
    const float* h_res  = (const float*)d_in[0];
    const float* x_true = (const float*)d_in[1];
    const float* padm   = (const float*)d_in[2];
    const float* ln_w   = (const float*)d_in[3];
    const float* ln_b   = (const float*)d_in[4];
    const float* wu_w   = (const float*)d_in[5];
    const float* wu_b   = (const float*)d_in[6];
    const float* wv_w   = (const float*)d_in[7];
    const float* wv_b   = (const float*)d_in[8];
    const float* wb_w   = (const float*)d_in[9];
    const float* wb_b   = (const float*)d_in[10];

    int BN = in_sizes[0] / D_MODEL;   // B*N
    int B = 2;
    int N = BN / B;

    transpose_kernel<<<(D_MODEL * 128) / 256, 256>>>(wu_w, wv_w);

    prep_kernel<<<BN / TR, 256>>>(h_res, ln_w, ln_b, wu_b, wv_b);

    main_kernel<<<BN, 128>>>(x_true, padm, wb_w, wb_b, B, N, (float*)d_out, BN);
}

// round 8
// speedup vs baseline: 1.1864x; 1.1864x over previous
#include <cuda_runtime.h>
#include <cuda_bf16.h>
#include <math.h>
#include <stdint.h>

#define D_MODEL 512
#define D_LOW   64
#define NUM_BINS 39
#define NB_PAD  40
#define DIST_MIN_F 2.0f
#define DIST_MAX_F 22.0f
#define BIN_W  ((DIST_MAX_F - DIST_MIN_F) / (float)(NUM_BINS - 1))
#define LN_EPS 1e-5f
#define MAX_ROWS 4096
#define JT 128

__device__ float g_U[MAX_ROWS * D_LOW];
__device__ unsigned long long g_Vb[MAX_ROWS * (D_LOW / 4)];  // 4 bf16 per u64
__device__ float g_Wt[D_MODEL * 128];
__device__ double g_ce[8];
__device__ unsigned int g_cnt[8];
__device__ unsigned int g_done;

__device__ __forceinline__ uint32_t smem_u32(const void* p) {
    uint32_t a;
    asm("{ .reg .u64 t; cvta.to.shared.u64 t, %1; cvt.u32.u64 %0, t; }" : "=r"(a) : "l"(p));
    return a;
}
#define CVT_BF2(res, lo, hi) \
    asm("cvt.rn.satfinite.bf16x2.f32 %0, %1, %2;" : "=r"(res) : "f"(hi), "f"(lo))
#define MULBF2(res, a, b) \
    asm("mul.bf16x2 %0, %1, %2;" : "=r"(res) : "r"(a), "r"(b))

#define LDSM_X4(r0, r1, r2, r3, addr) \
    asm volatile("ldmatrix.sync.aligned.m8n8.x4.shared.b16 {%0,%1,%2,%3}, [%4];" \
                 : "=r"(r0), "=r"(r1), "=r"(r2), "=r"(r3) : "r"(addr))

#define MMA_BF16(d, a0, a1, a2, a3, b0, b1) \
    asm volatile("mma.sync.aligned.m16n8k16.row.col.f32.bf16.bf16.f32 " \
                 "{%0,%1,%2,%3}, {%4,%5,%6,%7}, {%8,%9}, {%0,%1,%2,%3};" \
                 : "+f"((d)[0]), "+f"((d)[1]), "+f"((d)[2]), "+f"((d)[3]) \
                 : "r"(a0), "r"(a1), "r"(a2), "r"(a3), "r"(b0), "r"(b1))

// ---------------------------------------------------------------------------
// Kernel 0: transpose wu/wv into c-major Wt[512][128]; zero accumulators.
// ---------------------------------------------------------------------------
__global__ void __launch_bounds__(256) transpose_kernel(
    const float* __restrict__ wu_w, const float* __restrict__ wv_w)
{
    int idx = blockIdx.x * 256 + threadIdx.x;
    int c = idx >> 7;
    int o = idx & 127;
    float v = (o < D_LOW) ? wu_w[(size_t)o * D_MODEL + c]
                          : wv_w[(size_t)(o - D_LOW) * D_MODEL + c];
    g_Wt[idx] = v;
    if (idx < 8) { g_ce[idx] = 0.0; g_cnt[idx] = 0u; }
    if (idx == 8) g_done = 0u;
}

// ---------------------------------------------------------------------------
// Kernel 1: LayerNorm + projections. U -> fp32, V -> bf16 packed.
// ---------------------------------------------------------------------------
#define TR 16

__global__ void __launch_bounds__(256) prep_kernel(
    const float* __restrict__ h_res,
    const float* __restrict__ ln_w, const float* __restrict__ ln_b,
    const float* __restrict__ wu_b, const float* __restrict__ wv_b)
{
    __shared__ __align__(16) float sh[TR * D_MODEL];

    int t    = threadIdx.x;
    int warp = t >> 5;
    int lane = t & 31;

    #pragma unroll
    for (int rr = 0; rr < 2; rr++) {
        int lr  = warp * 2 + rr;
        size_t row = (size_t)blockIdx.x * TR + lr;
        const float4* hp = reinterpret_cast<const float4*>(h_res) + row * (D_MODEL / 4);
        float4 a[4];
        #pragma unroll
        for (int q = 0; q < 4; q++) a[q] = hp[lane + 32 * q];
        float s = 0.0f, sq = 0.0f;
        #pragma unroll
        for (int q = 0; q < 4; q++) {
            s  += a[q].x + a[q].y + a[q].z + a[q].w;
            sq += a[q].x*a[q].x + a[q].y*a[q].y + a[q].z*a[q].z + a[q].w*a[q].w;
        }
        #pragma unroll
        for (int o = 16; o > 0; o >>= 1) {
            s  += __shfl_xor_sync(0xffffffffu, s,  o);
            sq += __shfl_xor_sync(0xffffffffu, sq, o);
        }
        float mu   = s * (1.0f / (float)D_MODEL);
        float var  = sq * (1.0f / (float)D_MODEL) - mu * mu;
        float istd = rsqrtf(var + LN_EPS);

        const float4* wp = reinterpret_cast<const float4*>(ln_w);
        const float4* bp = reinterpret_cast<const float4*>(ln_b);
        float4* shp = reinterpret_cast<float4*>(sh) + lr * (D_MODEL / 4);
        #pragma unroll
        for (int q = 0; q < 4; q++) {
            float4 w4 = wp[lane + 32 * q];
            float4 b4 = bp[lane + 32 * q];
            float4 nv;
            nv.x = (a[q].x - mu) * istd * w4.x + b4.x;
            nv.y = (a[q].y - mu) * istd * w4.y + b4.y;
            nv.z = (a[q].z - mu) * istd * w4.z + b4.z;
            nv.w = (a[q].w - mu) * istd * w4.w + b4.w;
            shp[lane + 32 * q] = nv;
        }
    }
    __syncthreads();

    int tx = t & 31;
    int ty = t >> 5;
    int r0 = ty * 2, r1 = r0 + 1;

    float acc[8];
    #pragma unroll
    for (int q = 0; q < 8; q++) acc[q] = 0.0f;

    const float* sh0 = sh + r0 * D_MODEL;
    const float* sh1 = sh + r1 * D_MODEL;

    #pragma unroll 4
    for (int c = 0; c < D_MODEL; c++) {
        float4 w = *reinterpret_cast<const float4*>(g_Wt + c * 128 + tx * 4);
        float h0 = sh0[c];
        float h1 = sh1[c];
        acc[0] = fmaf(h0, w.x, acc[0]);
        acc[1] = fmaf(h0, w.y, acc[1]);
        acc[2] = fmaf(h0, w.z, acc[2]);
        acc[3] = fmaf(h0, w.w, acc[3]);
        acc[4] = fmaf(h1, w.x, acc[4]);
        acc[5] = fmaf(h1, w.y, acc[5]);
        acc[6] = fmaf(h1, w.z, acc[6]);
        acc[7] = fmaf(h1, w.w, acc[7]);
    }

    size_t grow0 = (size_t)blockIdx.x * TR + r0;
    size_t grow1 = grow0 + 1;
    int col = tx * 4;
    if (col < D_LOW) {
        float4 b = *reinterpret_cast<const float4*>(wu_b + col);
        float4 o0 = make_float4(acc[0] + b.x, acc[1] + b.y, acc[2] + b.z, acc[3] + b.w);
        float4 o1 = make_float4(acc[4] + b.x, acc[5] + b.y, acc[6] + b.z, acc[7] + b.w);
        *reinterpret_cast<float4*>(g_U + grow0 * D_LOW + col) = o0;
        *reinterpret_cast<float4*>(g_U + grow1 * D_LOW + col) = o1;
    } else {
        int vc = col - D_LOW;
        float4 b = *reinterpret_cast<const float4*>(wv_b + vc);
        float v0x = acc[0] + b.x, v0y = acc[1] + b.y, v0z = acc[2] + b.z, v0w = acc[3] + b.w;
        float v1x = acc[4] + b.x, v1y = acc[5] + b.y, v1z = acc[6] + b.z, v1w = acc[7] + b.w;
        uint32_t lo, hi;
        CVT_BF2(lo, v0x, v0y); CVT_BF2(hi, v0z, v0w);
        g_Vb[grow0 * 16 + (vc >> 2)] = (unsigned long long)lo | ((unsigned long long)hi << 32);
        CVT_BF2(lo, v1x, v1y); CVT_BF2(hi, v1z, v1w);
        g_Vb[grow1 * 16 + (vc >> 2)] = (unsigned long long)lo | ((unsigned long long)hi << 32);
    }
}

// ---------------------------------------------------------------------------
// Kernel 2: mma.sync bilinear + softmax-CE (R6 structure: D -> smem epilogue,
// single-pass maxless logsumexp). Last CTA finalizes the scalar.
// ---------------------------------------------------------------------------
#define WSTRIDE 144           // bytes per W row (128B data + 16B pad)
#define DSTRIDE 41            // floats per D row

__global__ void __launch_bounds__(128) main_kernel(
    const float* __restrict__ x_true, const float* __restrict__ pad,
    const float* __restrict__ wb_w,  const float* __restrict__ wb_b,
    int B, int N, float* __restrict__ out, int total_ctas)
{
    __shared__ uint4 s_V[JT * 9];                 // 18432 B
    __shared__ float s_WD[4][32 * DSTRIDE];       // 20992 B, W-tile / D-tile union
    __shared__ uint32_t s_Wb[NB_PAD * 32];        // 5120 B
    __shared__ uint32_t s_U[32];
    __shared__ float s_wbb[NUM_BINS];
    __shared__ float s_xi[4];
    __shared__ float s_red[4];
    __shared__ unsigned s_redc[4];

    int tid  = threadIdx.x;
    int wid  = tid >> 5;
    int lane = tid & 31;
    int g    = lane >> 2;       // group row
    int tig  = lane & 3;        // thread in group
    int r = blockIdx.x;         // b*N + i
    int b = r / N;

    for (int idx = tid; idx < NB_PAD * 32; idx += 128) {
        int row = idx >> 5, cp = idx & 31;
        float f0 = 0.0f, f1 = 0.0f;
        if (row < NUM_BINS) {
            f0 = wb_w[row * D_LOW + cp * 2];
            f1 = wb_w[row * D_LOW + cp * 2 + 1];
        }
        uint32_t v; CVT_BF2(v, f0, f1);
        s_Wb[idx] = v;
    }
    if (tid < 32) {
        float f0 = g_U[(size_t)r * D_LOW + tid * 2];
        float f1 = g_U[(size_t)r * D_LOW + tid * 2 + 1];
        uint32_t v; CVT_BF2(v, f0, f1);
        s_U[tid] = v;
    }
    if (tid < NUM_BINS) s_wbb[tid] = wb_b[tid];
    if (tid == 0) {
        size_t xb = (size_t)r * 3;
        s_xi[0] = x_true[xb]; s_xi[1] = x_true[xb + 1]; s_xi[2] = x_true[xb + 2];
        s_xi[3] = pad[r];
    }
    __syncthreads();

    // B fragments (constant across all chunks)
    uint32_t breg[40];
    #pragma unroll
    for (int ks = 0; ks < 4; ks++) {
        #pragma unroll
        for (int nt = 0; nt < 5; nt++) {
            int row = nt * 8 + g;
            int cp  = ks * 8 + tig;
            breg[ks * 10 + nt * 2 + 0] = s_Wb[row * 32 + cp];
            breg[ks * 10 + nt * 2 + 1] = s_Wb[row * 32 + cp + 4];
        }
    }

    float xi0 = s_xi[0], xi1 = s_xi[1], xi2 = s_xi[2], pi = s_xi[3];
    const uint4* u4 = reinterpret_cast<const uint4*>(s_U);
    float* sDw = s_WD[wid];
    char*  sWw = reinterpret_cast<char*>(s_WD[wid]);
    uint32_t sW_base = smem_u32(sWw);

    float cv = 0.0f; unsigned cc = 0u;
    int nchunks = (N + JT - 1) / JT;

    for (int jc = 0; jc < nchunks; jc++) {
        __syncwarp();
        int jw = jc * JT + wid * 32;      // this warp's first j

        // stage V rows jw..jw+31 (coalesced: 8 lanes per 128B row)
        {
            const uint4* src = reinterpret_cast<const uint4*>(g_Vb) + ((size_t)b * N) * 8;
            #pragma unroll
            for (int it = 0; it < 8; it++) {
                int idx = it * 32 + lane;
                int row = idx >> 3, q = idx & 7;
                int j = jw + row;
                uint4 v = make_uint4(0u, 0u, 0u, 0u);
                if (j < N) v = src[(size_t)j * 8 + q];
                s_V[(wid * 32 + row) * 9 + q] = v;
            }
        }
        __syncwarp();

        // W row for this lane's pair: W[lane][c] = U[c]*V[j][c] (bf16)
        {
            const uint4* vr = s_V + (wid * 32 + lane) * 9;
            #pragma unroll
            for (int q = 0; q < 8; q++) {
                uint4 vv = vr[q];
                uint4 uu = u4[q];
                uint4 w;
                MULBF2(w.x, vv.x, uu.x);
                MULBF2(w.y, vv.y, uu.y);
                MULBF2(w.z, vv.z, uu.z);
                MULBF2(w.w, vv.w, uu.w);
                *reinterpret_cast<uint4*>(sWw + lane * WSTRIDE + q * 16) = w;
            }
        }
        __syncwarp();

        // fragments + mma
        float acc[2][5][4];
        #pragma unroll
        for (int m = 0; m < 2; m++)
            #pragma unroll
            for (int nt = 0; nt < 5; nt++)
                #pragma unroll
                for (int q = 0; q < 4; q++) acc[m][nt][q] = 0.0f;

        #pragma unroll
        for (int m = 0; m < 2; m++) {
            #pragma unroll
            for (int ks = 0; ks < 4; ks++) {
                uint32_t a0, a1, a2, a3;
                uint32_t addr = sW_base + (uint32_t)((m * 16 + (lane & 15)) * WSTRIDE
                                                     + ks * 32 + (lane >> 4) * 16);
                LDSM_X4(a0, a1, a2, a3, addr);
                #pragma unroll
                for (int nt = 0; nt < 5; nt++)
                    MMA_BF16(acc[m][nt], a0, a1, a2, a3,
                             breg[ks * 10 + nt * 2], breg[ks * 10 + nt * 2 + 1]);
            }
        }
        __syncwarp();

        // D -> smem (pair-major, 41-float stride)
        #pragma unroll
        for (int m = 0; m < 2; m++) {
            int p0 = m * 16 + g;
            #pragma unroll
            for (int nt = 0; nt < 5; nt++) {
                int col = nt * 8 + tig * 2;
                sDw[p0 * DSTRIDE + col]           = acc[m][nt][0];
                sDw[p0 * DSTRIDE + col + 1]       = acc[m][nt][1];
                sDw[(p0 + 8) * DSTRIDE + col]     = acc[m][nt][2];
                sDw[(p0 + 8) * DSTRIDE + col + 1] = acc[m][nt][3];
            }
        }
        __syncwarp();

        // epilogue: pair = lane, single-pass maxless logsumexp
        int j = jw + lane;
        float xj0 = 0.f, xj1 = 0.f, xj2 = 0.f, pj = 0.f;
        if (j < N) {
            size_t xb = ((size_t)b * N + j) * 3;
            xj0 = x_true[xb]; xj1 = x_true[xb + 1]; xj2 = x_true[xb + 2];
            pj = pad[(size_t)b * N + j];
        }
        const float* lrow = sDw + lane * DSTRIDE;

        float dx = xi0 - xj0, dy = xi1 - xj1, dz = xi2 - xj2;
        float dist = sqrtf(dx * dx + dy * dy + dz * dz);
        int bin = (int)((dist - DIST_MIN_F) / BIN_W);
        bin = min(max(bin, 0), NUM_BINS - 1);

        float ssum = 0.0f, tl = 0.0f;
        #pragma unroll
        for (int k = 0; k < NUM_BINS; k++) {
            float lv = lrow[k] + s_wbb[k];
            ssum += __expf(lv);
            if (k == bin) tl = lv;
        }
        float ce = __logf(ssum) - tl;

        bool ok = (j < N) && (pi * pj > 0.0f);
        cv += ok ? ce : 0.0f;
        cc += ok ? 1u : 0u;
    }

    #pragma unroll
    for (int o = 16; o > 0; o >>= 1) {
        cv += __shfl_down_sync(0xffffffffu, cv, o);
        cc += __shfl_down_sync(0xffffffffu, cc, o);
    }
    if (lane == 0) { s_red[wid] = cv; s_redc[wid] = cc; }
    __syncthreads();
    if (tid == 0) {
        float S = s_red[0] + s_red[1] + s_red[2] + s_red[3];
        unsigned C = s_redc[0] + s_redc[1] + s_redc[2] + s_redc[3];
        atomicAdd(&g_ce[b], (double)S);
        atomicAdd(&g_cnt[b], C);
        __threadfence();
        unsigned done = atomicAdd(&g_done, 1u);
        if (done == (unsigned)(total_ctas - 1)) {
            __threadfence();
            double loss = 0.0;
            int valid = 0;
            for (int bb = 0; bb < B; bb++) {
                if (g_cnt[bb] > 0u) { loss += g_ce[bb] / (double)g_cnt[bb]; valid++; }
            }
            out[0] = (float)(valid > 0 ? loss / (double)valid : 0.0);
        }
    }
}

// ---------------------------------------------------------------------------
extern "C" void kernel_launch(void* const* d_in, const int* in_sizes, int n_in,
                              void* d_out, int out_size)
{
    const float* h_res  = (const float*)d_in[0];
    const float* x_true = (const float*)d_in[1];
    const float* padm   = (const float*)d_in[2];
    const float* ln_w   = (const float*)d_in[3];
    const float* ln_b   = (const float*)d_in[4];
    const float* wu_w   = (const float*)d_in[5];
    const float* wu_b   = (const float*)d_in[6];
    const float* wv_w   = (const float*)d_in[7];
    const float* wv_b   = (const float*)d_in[8];
    const float* wb_w   = (const float*)d_in[9];
    const float* wb_b   = (const float*)d_in[10];

    int BN = in_sizes[0] / D_MODEL;   // B*N
    int B = 2;
    int N = BN / B;

    transpose_kernel<<<(D_MODEL * 128) / 256, 256>>>(wu_w, wv_w);

    prep_kernel<<<BN / TR, 256>>>(h_res, ln_b ? ln_w : ln_w, ln_b, wu_b, wv_b);

    main_kernel<<<BN, 128>>>(x_true, padm, wb_w, wb_b, B, N, (float*)d_out, BN);
}